// round 15
// baseline (speedup 1.0000x reference)
#include <cuda_runtime.h>
#include <cuda_bf16.h>
#include <cstdint>
#include <math.h>

#define BB 128
#define DD 128
#define QQ 256
#define LL 1024
#define TEMP 4.0f

#define NCHUNK 4
#define BCH (BB / NCHUNK)   // 32 batches per pipeline chunk

#define QUERY_ELEMS ((size_t)BB * DD * QQ)
#define WC_ELEMS    ((size_t)BB * DD * QQ)
#define AMAP_ELEMS  ((size_t)BB * QQ * LL)

__device__ __align__(16) float g_attn_q[(size_t)BB * LL * QQ];
__device__ __align__(16) float g_scratch_amap[AMAP_ELEMS];
__device__ __align__(16) float g_scratch_wc[WC_ELEMS];

// ============================ helpers ======================================
__device__ __forceinline__ uint32_t smem_u32(const void* p) {
    uint32_t a;
    asm("{ .reg .u64 t; cvta.to.shared.u64 t, %1; cvt.u32.u64 %0, t; }"
        : "=r"(a) : "l"(p));
    return a;
}
__device__ __forceinline__ uint32_t pack2bf(float x, float y) {
    __nv_bfloat162 h = __floats2bfloat162_rn(x, y);
    return *(uint32_t*)&h;
}
__device__ __forceinline__ void split2(float x, float y,
                                       uint32_t& hi, uint32_t& lo) {
    __nv_bfloat16 hx = __float2bfloat16_rn(x);
    __nv_bfloat16 hy = __float2bfloat16_rn(y);
    float rx = x - __bfloat162float(hx);
    float ry = y - __bfloat162float(hy);
    __nv_bfloat162 h2; h2.x = hx; h2.y = hy;
    hi = *(uint32_t*)&h2;
    lo = pack2bf(rx, ry);
}
#define LDMATRIX_X4(r0, r1, r2, r3, addr) \
    asm volatile("ldmatrix.sync.aligned.m8n8.x4.shared.b16 {%0,%1,%2,%3}, [%4];" \
                 : "=r"(r0), "=r"(r1), "=r"(r2), "=r"(r3) : "r"(addr))
#define LDMATRIX_X4_T(r0, r1, r2, r3, addr) \
    asm volatile("ldmatrix.sync.aligned.m8n8.x4.trans.shared.b16 {%0,%1,%2,%3}, [%4];" \
                 : "=r"(r0), "=r"(r1), "=r"(r2), "=r"(r3) : "r"(addr))
#define MMA_BF16(c, a0, a1, a2, a3, b0, b1) \
    asm volatile("mma.sync.aligned.m16n8k16.row.col.f32.bf16.bf16.f32 " \
                 "{%0,%1,%2,%3}, {%4,%5,%6,%7}, {%8,%9}, {%0,%1,%2,%3};" \
                 : "+f"((c)[0]), "+f"((c)[1]), "+f"((c)[2]), "+f"((c)[3]) \
                 : "r"(a0), "r"(a1), "r"(a2), "r"(a3), "r"(b0), "r"(b1))

// ---------------------------------------------------------------------------
// Kernel 1 v4 (chunked + double-buffered) — identical math to R13, +b0 offset.
// ---------------------------------------------------------------------------
#define K1C_AHI 0
#define K1C_ALO 1152
#define K1C_BHI 2304
#define K1C_BLO 6528
#define K1_STAGE_U 10752
#define K1_SMEM_BYTES (2 * K1_STAGE_U * 4)   // 86016 B

__global__ __launch_bounds__(512, 1)
void k1_mma(const float* __restrict__ query,
            const float* __restrict__ ctx, int b0) {
    extern __shared__ __align__(16) char smc[];
    uint32_t* smu = (uint32_t*)smc;
    const uint32_t sb = smem_u32(smc);

    const int tid  = threadIdx.x;
    const int lane = tid & 31;
    const int wid  = tid >> 5;
    const int wm   = wid & 1;
    const int wn   = wid >> 1;

    const int b  = blockIdx.y + b0;
    const int l0 = blockIdx.x * 64;

    const float* ctxb = ctx + (size_t)b * DD * LL;
    const float* qb   = query + (size_t)b * DD * QQ;

    const int a_fl = tid & 15;
    const int a_dr = tid >> 4;
    const int b_fq = tid & 63;
    const int b_dr = tid >> 6;

    float4 pa, pb0, pb1, pb2, pb3;

#define K1_LD(c) do { \
        const int _d0 = (c) * 32; \
        pa  = *(const float4*)(ctxb + (size_t)(_d0 + a_dr) * LL + l0 + a_fl * 4); \
        pb0 = *(const float4*)(qb + (size_t)(_d0 + b_dr)      * QQ + b_fq * 4); \
        pb1 = *(const float4*)(qb + (size_t)(_d0 + b_dr +  8) * QQ + b_fq * 4); \
        pb2 = *(const float4*)(qb + (size_t)(_d0 + b_dr + 16) * QQ + b_fq * 4); \
        pb3 = *(const float4*)(qb + (size_t)(_d0 + b_dr + 24) * QQ + b_fq * 4); \
    } while (0)

#define K1_ST1(v, base, row, stride_u, lo_delta, col) do { \
        uint32_t _h0, _o0, _h1, _o1; \
        split2((v).x, (v).y, _h0, _o0); \
        split2((v).z, (v).w, _h1, _o1); \
        uint32_t* _p = stp + (base) + (row) * (stride_u) + (col) * 2; \
        _p[0] = _h0; _p[1] = _h1; \
        _p[(lo_delta)] = _o0; _p[(lo_delta) + 1] = _o1; \
    } while (0)

#define K1_ST(s) do { \
        uint32_t* stp = smu + (s) * K1_STAGE_U; \
        K1_ST1(pa,  K1C_AHI, a_dr,      36,  (K1C_ALO - K1C_AHI), a_fl); \
        K1_ST1(pb0, K1C_BHI, b_dr,      132, (K1C_BLO - K1C_BHI), b_fq); \
        K1_ST1(pb1, K1C_BHI, b_dr + 8,  132, (K1C_BLO - K1C_BHI), b_fq); \
        K1_ST1(pb2, K1C_BHI, b_dr + 16, 132, (K1C_BLO - K1C_BHI), b_fq); \
        K1_ST1(pb3, K1C_BHI, b_dr + 24, 132, (K1C_BLO - K1C_BHI), b_fq); \
    } while (0)

    float acc[2][4][4];
    #pragma unroll
    for (int i = 0; i < 2; i++)
        #pragma unroll
        for (int j = 0; j < 4; j++)
            #pragma unroll
            for (int k = 0; k < 4; k++) acc[i][j][k] = 0.0f;

    const int krA = ((lane >> 4) << 3) + (lane & 7);
    const int mcs = (((lane >> 3) & 1) << 3);
    const int krB = (((lane >> 3) & 1) << 3) + (lane & 7);
    const int ncs = ((lane >> 4) << 3);

    K1_LD(0);
    K1_ST(0);
    __syncthreads();

    for (int c = 0; c < 4; c++) {
        if (c < 3) K1_LD(c + 1);

        const uint32_t stage_b = sb + (uint32_t)(c & 1) * (K1_STAGE_U * 4);
        #pragma unroll
        for (int ks = 0; ks < 2; ks++) {
            uint32_t ah[2][4], al[2][4];
            #pragma unroll
            for (int mt = 0; mt < 2; mt++) {
                int mcol = wm * 32 + mt * 16 + mcs;
                uint32_t ad = stage_b + K1C_AHI * 4
                            + (uint32_t)(ks * 16 + krA) * 144 + mcol * 2;
                LDMATRIX_X4_T(ah[mt][0], ah[mt][1], ah[mt][2], ah[mt][3], ad);
                LDMATRIX_X4_T(al[mt][0], al[mt][1], al[mt][2], al[mt][3],
                              ad + (K1C_ALO - K1C_AHI) * 4);
            }
            #pragma unroll
            for (int j = 0; j < 2; j++) {
                int ncol = wn * 32 + j * 16 + ncs;
                uint32_t bd = stage_b + K1C_BHI * 4
                            + (uint32_t)(ks * 16 + krB) * 528 + ncol * 2;
                uint32_t bh0, bh1, bh2, bh3, bl0, bl1, bl2, bl3;
                LDMATRIX_X4_T(bh0, bh1, bh2, bh3, bd);
                LDMATRIX_X4_T(bl0, bl1, bl2, bl3, bd + (K1C_BLO - K1C_BHI) * 4);
                #pragma unroll
                for (int mt = 0; mt < 2; mt++) {
                    MMA_BF16(acc[mt][j * 2],     ah[mt][0], ah[mt][1], ah[mt][2], ah[mt][3], bh0, bh1);
                    MMA_BF16(acc[mt][j * 2 + 1], ah[mt][0], ah[mt][1], ah[mt][2], ah[mt][3], bh2, bh3);
                    MMA_BF16(acc[mt][j * 2],     ah[mt][0], ah[mt][1], ah[mt][2], ah[mt][3], bl0, bl1);
                    MMA_BF16(acc[mt][j * 2 + 1], ah[mt][0], ah[mt][1], ah[mt][2], ah[mt][3], bl2, bl3);
                    MMA_BF16(acc[mt][j * 2],     al[mt][0], al[mt][1], al[mt][2], al[mt][3], bh0, bh1);
                    MMA_BF16(acc[mt][j * 2 + 1], al[mt][0], al[mt][1], al[mt][2], al[mt][3], bh2, bh3);
                }
            }
        }

        if (c < 3) K1_ST((c + 1) & 1);
        __syncthreads();
    }

    float* sc = (float*)smc;
    const int gid = lane >> 2;
    const int tig = lane & 3;
    #pragma unroll
    for (int mt = 0; mt < 2; mt++) {
        int r0 = wm * 32 + mt * 16 + gid;
        #pragma unroll
        for (int nt = 0; nt < 4; nt++) {
            int q = wn * 32 + nt * 8 + tig * 2;
            *(float2*)(sc + (size_t)r0 * 260 + q) =
                make_float2(acc[mt][nt][0], acc[mt][nt][1]);
            *(float2*)(sc + (size_t)(r0 + 8) * 260 + q) =
                make_float2(acc[mt][nt][2], acc[mt][nt][3]);
        }
    }
    __syncthreads();

    const size_t outb = ((size_t)b * LL + l0 + wid * 4) * QQ;
    #pragma unroll
    for (int i = 0; i < 4; i++) {
        const float* row = sc + (size_t)(wid * 4 + i) * 260;
        float e[8];
        float m = -1e30f;
        #pragma unroll
        for (int j = 0; j < 8; j++) { e[j] = row[lane + j * 32]; m = fmaxf(m, e[j]); }
        #pragma unroll
        for (int o = 16; o; o >>= 1) m = fmaxf(m, __shfl_xor_sync(0xffffffffu, m, o));
        float s = 0.0f;
        #pragma unroll
        for (int j = 0; j < 8; j++) { e[j] = __expf(e[j] - m); s += e[j]; }
        #pragma unroll
        for (int o = 16; o; o >>= 1) s += __shfl_xor_sync(0xffffffffu, s, o);
        float inv = 1.0f / s;
        #pragma unroll
        for (int j = 0; j < 8; j++)
            g_attn_q[outb + (size_t)i * QQ + lane + j * 32] = e[j] * inv;
    }
}

// ---------------------------------------------------------------------------
// Kernel 3 — identical math, +b0 offset.
// ---------------------------------------------------------------------------
__global__ void k3_softmax_l(float* __restrict__ amap, int b0) {
    extern __shared__ float sm3[];
    const int tid  = threadIdx.x;
    const int b    = blockIdx.y + b0;
    const int q0   = blockIdx.x * 32;
    const int w    = tid >> 5;
    const int lane = tid & 31;

    const float* src = g_attn_q + (size_t)b * LL * QQ + q0;
    #pragma unroll
    for (int i = 0; i < 32; i++) {
        int l = i * 32 + w;
        sm3[lane * 1025 + l] = src[(size_t)l * QQ + lane];
    }
    __syncthreads();

    const float* row = sm3 + w * 1025;
    float e[32];
    float mx = -1e30f;
    #pragma unroll
    for (int i = 0; i < 32; i++) {
        float v = TEMP * row[lane + 32 * i];
        e[i] = v;
        mx = fmaxf(mx, v);
    }
    #pragma unroll
    for (int o = 16; o; o >>= 1) mx = fmaxf(mx, __shfl_xor_sync(0xffffffffu, mx, o));
    float s = 0.0f;
    #pragma unroll
    for (int i = 0; i < 32; i++) { e[i] = __expf(e[i] - mx); s += e[i]; }
    #pragma unroll
    for (int o = 16; o; o >>= 1) s += __shfl_xor_sync(0xffffffffu, s, o);
    float inv = 1.0f / s;

    float* dst = amap + ((size_t)b * QQ + q0 + w) * LL;
    #pragma unroll
    for (int i = 0; i < 32; i++) dst[lane + 32 * i] = e[i] * inv;
}

// ---------------------------------------------------------------------------
// Kernel 4 v2 — identical math, +b0 offset.
// ---------------------------------------------------------------------------
#define KC    32
#define NCH   (LL / KC)
#define ROWU  20
#define AHI_O 0
#define ALO_O (64 * ROWU)
#define BHI_O (2 * 64 * ROWU)
#define BLO_O (2 * 64 * ROWU + 128 * ROWU)
#define K4_STAGE_U 7680
#define K4_SMEM_BYTES (2 * K4_STAGE_U * 4)

__global__ __launch_bounds__(256, 2)
void k4_mma(const float* __restrict__ ctx,
            const float* __restrict__ amap,
            float* __restrict__ wc, int b0) {
    extern __shared__ __align__(16) uint32_t sm4[];
    const uint32_t sb = smem_u32(sm4);

    const int tid  = threadIdx.x;
    const int lane = tid & 31;
    const int wid  = tid >> 5;
    const int wm   = wid & 1;
    const int wn   = wid >> 1;

    const int b  = blockIdx.y + b0;
    const int d0 = (blockIdx.x & 1) * 64;
    const int q0 = (blockIdx.x >> 1) * 128;

    const float* A  = ctx  + (size_t)b * DD * LL + (size_t)d0 * LL;
    const float* Bm = amap + ((size_t)b * QQ + q0) * LL;

    const int frow = tid >> 3;
    const int ff   = tid & 7;

    float4 pa0, pa1, pb0, pb1, pb2, pb3;

#define K4_LD(c) do { \
        const int _l0 = (c) * KC; \
        pa0 = *(const float4*)(A  + (size_t)(frow)      * LL + _l0 + ff * 4); \
        pa1 = *(const float4*)(A  + (size_t)(frow + 32) * LL + _l0 + ff * 4); \
        pb0 = *(const float4*)(Bm + (size_t)(frow)      * LL + _l0 + ff * 4); \
        pb1 = *(const float4*)(Bm + (size_t)(frow + 32) * LL + _l0 + ff * 4); \
        pb2 = *(const float4*)(Bm + (size_t)(frow + 64) * LL + _l0 + ff * 4); \
        pb3 = *(const float4*)(Bm + (size_t)(frow + 96) * LL + _l0 + ff * 4); \
    } while (0)

#define K4_ST1(v, base, row, lo_delta) do { \
        uint32_t _h0, _o0, _h1, _o1; \
        split2((v).x, (v).y, _h0, _o0); \
        split2((v).z, (v).w, _h1, _o1); \
        uint32_t* _p = stp + (base) + (row) * ROWU + ff * 2; \
        _p[0] = _h0; _p[1] = _h1; \
        _p[(lo_delta)] = _o0; _p[(lo_delta) + 1] = _o1; \
    } while (0)

#define K4_ST(s) do { \
        uint32_t* stp = sm4 + (s) * K4_STAGE_U; \
        K4_ST1(pa0, AHI_O, frow,       (ALO_O - AHI_O)); \
        K4_ST1(pa1, AHI_O, frow + 32,  (ALO_O - AHI_O)); \
        K4_ST1(pb0, BHI_O, frow,       (BLO_O - BHI_O)); \
        K4_ST1(pb1, BHI_O, frow + 32,  (BLO_O - BHI_O)); \
        K4_ST1(pb2, BHI_O, frow + 64,  (BLO_O - BHI_O)); \
        K4_ST1(pb3, BHI_O, frow + 96,  (BLO_O - BHI_O)); \
    } while (0)

    float acc[2][4][4];
    #pragma unroll
    for (int i = 0; i < 2; i++)
        #pragma unroll
        for (int j = 0; j < 4; j++)
            #pragma unroll
            for (int k = 0; k < 4; k++) acc[i][j][k] = 0.0f;

    const uint32_t a_row = wm * 32 + (lane & 15);
    const uint32_t a_col = (lane >> 4) * 16;
    const uint32_t b_rowbase = wn * 32 + ((lane >> 4) << 3) + (lane & 7);
    const uint32_t b_col = ((lane >> 3) & 1) * 16;

    K4_LD(0);
    K4_ST(0);
    __syncthreads();

    for (int c = 0; c < NCH; c++) {
        if (c < NCH - 1) K4_LD(c + 1);

        const uint32_t stage_b = sb + (uint32_t)(c & 1) * (K4_STAGE_U * 4);
        #pragma unroll
        for (int ks = 0; ks < 2; ks++) {
            const uint32_t kbyte = ks * 32;
            uint32_t ah[2][4], al[2][4];
            #pragma unroll
            for (int mt = 0; mt < 2; mt++) {
                uint32_t addr = stage_b + 4 * (AHI_O + (a_row + mt * 16) * ROWU)
                              + kbyte + a_col;
                LDMATRIX_X4(ah[mt][0], ah[mt][1], ah[mt][2], ah[mt][3], addr);
                addr += 4 * (ALO_O - AHI_O);
                LDMATRIX_X4(al[mt][0], al[mt][1], al[mt][2], al[mt][3], addr);
            }
            uint32_t bh[4][2], bl[4][2];
            #pragma unroll
            for (int p = 0; p < 2; p++) {
                uint32_t addr = stage_b + 4 * (BHI_O + (b_rowbase + p * 16) * ROWU)
                              + kbyte + b_col;
                LDMATRIX_X4(bh[p * 2][0], bh[p * 2][1],
                            bh[p * 2 + 1][0], bh[p * 2 + 1][1], addr);
                addr += 4 * (BLO_O - BHI_O);
                LDMATRIX_X4(bl[p * 2][0], bl[p * 2][1],
                            bl[p * 2 + 1][0], bl[p * 2 + 1][1], addr);
            }
            #pragma unroll
            for (int mt = 0; mt < 2; mt++)
                #pragma unroll
                for (int nt = 0; nt < 4; nt++)
                    MMA_BF16(acc[mt][nt], ah[mt][0], ah[mt][1], ah[mt][2],
                             ah[mt][3], bh[nt][0], bh[nt][1]);
            #pragma unroll
            for (int mt = 0; mt < 2; mt++)
                #pragma unroll
                for (int nt = 0; nt < 4; nt++)
                    MMA_BF16(acc[mt][nt], ah[mt][0], ah[mt][1], ah[mt][2],
                             ah[mt][3], bl[nt][0], bl[nt][1]);
            #pragma unroll
            for (int mt = 0; mt < 2; mt++)
                #pragma unroll
                for (int nt = 0; nt < 4; nt++)
                    MMA_BF16(acc[mt][nt], al[mt][0], al[mt][1], al[mt][2],
                             al[mt][3], bh[nt][0], bh[nt][1]);
        }

        if (c < NCH - 1) K4_ST((c + 1) & 1);
        __syncthreads();
    }

    float* outb = wc + (size_t)b * DD * QQ;
    const int gid = lane >> 2;
    const int tig = lane & 3;
    #pragma unroll
    for (int mt = 0; mt < 2; mt++) {
        #pragma unroll
        for (int nt = 0; nt < 4; nt++) {
            int d = d0 + wm * 32 + mt * 16 + gid;
            int q = q0 + wn * 32 + nt * 8 + tig * 2;
            *(float2*)(outb + (size_t)d * QQ + q) =
                make_float2(acc[mt][nt][0], acc[mt][nt][1]);
            *(float2*)(outb + (size_t)(d + 8) * QQ + q) =
                make_float2(acc[mt][nt][2], acc[mt][nt][3]);
        }
    }
}

// ---------------------------------------------------------------------------
// Launch: batch-chunked 3-stream pipeline. Streams/events are created ONCE on
// the first call (before graph capture begins) and reused forever, so no
// device-memory movement happens during capture. GPU work per call is
// identical and deterministic.
// ---------------------------------------------------------------------------
extern "C" void kernel_launch(void* const* d_in, const int* in_sizes, int n_in,
                              void* d_out, int out_size) {
    const float* query;
    const float* ctx;
    if ((size_t)in_sizes[0] == QUERY_ELEMS) {
        query = (const float*)d_in[0];
        ctx   = (const float*)d_in[1];
    } else {
        query = (const float*)d_in[1];
        ctx   = (const float*)d_in[0];
    }

    float* wc;
    float* amap;
    void* sym;
    if ((size_t)out_size >= WC_ELEMS + AMAP_ELEMS) {
        wc   = (float*)d_out;
        amap = (float*)d_out + WC_ELEMS;
    } else if ((size_t)out_size == WC_ELEMS) {
        wc = (float*)d_out;
        cudaGetSymbolAddress(&sym, g_scratch_amap);
        amap = (float*)sym;
    } else {
        cudaGetSymbolAddress(&sym, g_scratch_wc);
        wc = (float*)sym;
        amap = (float*)d_out;
    }

    const int SMEM_K3 = (32 * 1025) * sizeof(float);

    // --- one-time host-side resources (created before capture, reused) ---
    static bool inited = false;
    static cudaStream_t sA, sB, sC;
    static cudaEvent_t evFork, ev1[NCHUNK], ev3[NCHUNK], evA, evB, evC;
    if (!inited) {
        cudaStreamCreateWithFlags(&sA, cudaStreamNonBlocking);
        cudaStreamCreateWithFlags(&sB, cudaStreamNonBlocking);
        cudaStreamCreateWithFlags(&sC, cudaStreamNonBlocking);
        cudaEventCreateWithFlags(&evFork, cudaEventDisableTiming);
        for (int c = 0; c < NCHUNK; c++) {
            cudaEventCreateWithFlags(&ev1[c], cudaEventDisableTiming);
            cudaEventCreateWithFlags(&ev3[c], cudaEventDisableTiming);
        }
        cudaEventCreateWithFlags(&evA, cudaEventDisableTiming);
        cudaEventCreateWithFlags(&evB, cudaEventDisableTiming);
        cudaEventCreateWithFlags(&evC, cudaEventDisableTiming);

        cudaFuncSetAttribute(k1_mma,
                             cudaFuncAttributeMaxDynamicSharedMemorySize, K1_SMEM_BYTES);
        cudaFuncSetAttribute(k3_softmax_l,
                             cudaFuncAttributeMaxDynamicSharedMemorySize, SMEM_K3);
        cudaFuncSetAttribute(k4_mma,
                             cudaFuncAttributeMaxDynamicSharedMemorySize, K4_SMEM_BYTES);
        inited = true;
    }

    // fork from the (possibly capturing) legacy stream
    cudaEventRecord(evFork, 0);
    cudaStreamWaitEvent(sA, evFork, 0);
    cudaStreamWaitEvent(sB, evFork, 0);
    cudaStreamWaitEvent(sC, evFork, 0);

    for (int c = 0; c < NCHUNK; c++) {
        const int b0 = c * BCH;
        k1_mma<<<dim3(LL / 64, BCH), 512, K1_SMEM_BYTES, sA>>>(query, ctx, b0);
        cudaEventRecord(ev1[c], sA);

        cudaStreamWaitEvent(sB, ev1[c], 0);
        k3_softmax_l<<<dim3(QQ / 32, BCH), 1024, SMEM_K3, sB>>>(amap, b0);
        cudaEventRecord(ev3[c], sB);

        cudaStreamWaitEvent(sC, ev3[c], 0);
        k4_mma<<<dim3(4, BCH), 256, K4_SMEM_BYTES, sC>>>(ctx, amap, wc, b0);
    }

    // join all pipeline streams back into the legacy stream
    cudaEventRecord(evA, sA);
    cudaEventRecord(evB, sB);
    cudaEventRecord(evC, sC);
    cudaStreamWaitEvent(0, evA, 0);
    cudaStreamWaitEvent(0, evB, 0);
    cudaStreamWaitEvent(0, evC, 0);
}

// round 16
// speedup vs baseline: 1.0441x; 1.0441x over previous
#include <cuda_runtime.h>
#include <cuda_bf16.h>
#include <cstdint>
#include <math.h>

#define BB 128
#define DD 128
#define QQ 256
#define LL 1024
#define TEMP 4.0f

#define QUERY_ELEMS ((size_t)BB * DD * QQ)
#define WC_ELEMS    ((size_t)BB * DD * QQ)
#define AMAP_ELEMS  ((size_t)BB * QQ * LL)

// g_attn_q is stored TRANSPOSED: [b][q][l]
__device__ __align__(16) float g_attn_q[(size_t)BB * QQ * LL];
__device__ __align__(16) float g_scratch_amap[AMAP_ELEMS];
__device__ __align__(16) float g_scratch_wc[WC_ELEMS];

// ============================ helpers ======================================
__device__ __forceinline__ uint32_t smem_u32(const void* p) {
    uint32_t a;
    asm("{ .reg .u64 t; cvta.to.shared.u64 t, %1; cvt.u32.u64 %0, t; }"
        : "=r"(a) : "l"(p));
    return a;
}
__device__ __forceinline__ uint32_t pack2bf(float x, float y) {
    __nv_bfloat162 h = __floats2bfloat162_rn(x, y);
    return *(uint32_t*)&h;
}
__device__ __forceinline__ void split2(float x, float y,
                                       uint32_t& hi, uint32_t& lo) {
    __nv_bfloat16 hx = __float2bfloat16_rn(x);
    __nv_bfloat16 hy = __float2bfloat16_rn(y);
    float rx = x - __bfloat162float(hx);
    float ry = y - __bfloat162float(hy);
    __nv_bfloat162 h2; h2.x = hx; h2.y = hy;
    hi = *(uint32_t*)&h2;
    lo = pack2bf(rx, ry);
}
#define LDMATRIX_X4(r0, r1, r2, r3, addr) \
    asm volatile("ldmatrix.sync.aligned.m8n8.x4.shared.b16 {%0,%1,%2,%3}, [%4];" \
                 : "=r"(r0), "=r"(r1), "=r"(r2), "=r"(r3) : "r"(addr))
#define LDMATRIX_X4_T(r0, r1, r2, r3, addr) \
    asm volatile("ldmatrix.sync.aligned.m8n8.x4.trans.shared.b16 {%0,%1,%2,%3}, [%4];" \
                 : "=r"(r0), "=r"(r1), "=r"(r2), "=r"(r3) : "r"(addr))
#define MMA_BF16(c, a0, a1, a2, a3, b0, b1) \
    asm volatile("mma.sync.aligned.m16n8k16.row.col.f32.bf16.bf16.f32 " \
                 "{%0,%1,%2,%3}, {%4,%5,%6,%7}, {%8,%9}, {%0,%1,%2,%3};" \
                 : "+f"((c)[0]), "+f"((c)[1]), "+f"((c)[2]), "+f"((c)[3]) \
                 : "r"(a0), "r"(a1), "r"(a2), "r"(a3), "r"(b0), "r"(b1))

// ---------------------------------------------------------------------------
// Kernel 1 v5: chunked/double-buffered HMMA (R13) + fused softmax-q epilogue
// that writes g_attn_q TRANSPOSED via in-smem column reads (stride 261,
// conflict-free). CTA 64(l) x 256(q), K=128(d), 512 threads, grid (16, B).
// ---------------------------------------------------------------------------
#define K1C_AHI 0
#define K1C_ALO 1152
#define K1C_BHI 2304
#define K1C_BLO 6528
#define K1_STAGE_U 10752
#define K1_SMEM_BYTES (2 * K1_STAGE_U * 4)   // 86016 B (>= 64*261*4 = 66816)

__global__ __launch_bounds__(512, 1)
void k1_mma(const float* __restrict__ query,
            const float* __restrict__ ctx) {
    extern __shared__ __align__(16) char smc[];
    uint32_t* smu = (uint32_t*)smc;
    const uint32_t sb = smem_u32(smc);

    const int tid  = threadIdx.x;
    const int lane = tid & 31;
    const int wid  = tid >> 5;
    const int wm   = wid & 1;
    const int wn   = wid >> 1;

    const int b  = blockIdx.y;
    const int l0 = blockIdx.x * 64;

    const float* ctxb = ctx + (size_t)b * DD * LL;
    const float* qb   = query + (size_t)b * DD * QQ;

    const int a_fl = tid & 15;
    const int a_dr = tid >> 4;
    const int b_fq = tid & 63;
    const int b_dr = tid >> 6;

    float4 pa, pb0, pb1, pb2, pb3;

#define K1_LD(c) do { \
        const int _d0 = (c) * 32; \
        pa  = *(const float4*)(ctxb + (size_t)(_d0 + a_dr) * LL + l0 + a_fl * 4); \
        pb0 = *(const float4*)(qb + (size_t)(_d0 + b_dr)      * QQ + b_fq * 4); \
        pb1 = *(const float4*)(qb + (size_t)(_d0 + b_dr +  8) * QQ + b_fq * 4); \
        pb2 = *(const float4*)(qb + (size_t)(_d0 + b_dr + 16) * QQ + b_fq * 4); \
        pb3 = *(const float4*)(qb + (size_t)(_d0 + b_dr + 24) * QQ + b_fq * 4); \
    } while (0)

#define K1_ST1(v, base, row, stride_u, lo_delta, col) do { \
        uint32_t _h0, _o0, _h1, _o1; \
        split2((v).x, (v).y, _h0, _o0); \
        split2((v).z, (v).w, _h1, _o1); \
        uint32_t* _p = stp + (base) + (row) * (stride_u) + (col) * 2; \
        _p[0] = _h0; _p[1] = _h1; \
        _p[(lo_delta)] = _o0; _p[(lo_delta) + 1] = _o1; \
    } while (0)

#define K1_ST(s) do { \
        uint32_t* stp = smu + (s) * K1_STAGE_U; \
        K1_ST1(pa,  K1C_AHI, a_dr,      36,  (K1C_ALO - K1C_AHI), a_fl); \
        K1_ST1(pb0, K1C_BHI, b_dr,      132, (K1C_BLO - K1C_BHI), b_fq); \
        K1_ST1(pb1, K1C_BHI, b_dr + 8,  132, (K1C_BLO - K1C_BHI), b_fq); \
        K1_ST1(pb2, K1C_BHI, b_dr + 16, 132, (K1C_BLO - K1C_BHI), b_fq); \
        K1_ST1(pb3, K1C_BHI, b_dr + 24, 132, (K1C_BLO - K1C_BHI), b_fq); \
    } while (0)

    float acc[2][4][4];
    #pragma unroll
    for (int i = 0; i < 2; i++)
        #pragma unroll
        for (int j = 0; j < 4; j++)
            #pragma unroll
            for (int k = 0; k < 4; k++) acc[i][j][k] = 0.0f;

    const int krA = ((lane >> 4) << 3) + (lane & 7);
    const int mcs = (((lane >> 3) & 1) << 3);
    const int krB = (((lane >> 3) & 1) << 3) + (lane & 7);
    const int ncs = ((lane >> 4) << 3);

    K1_LD(0);
    K1_ST(0);
    __syncthreads();

    for (int c = 0; c < 4; c++) {
        if (c < 3) K1_LD(c + 1);

        const uint32_t stage_b = sb + (uint32_t)(c & 1) * (K1_STAGE_U * 4);
        #pragma unroll
        for (int ks = 0; ks < 2; ks++) {
            uint32_t ah[2][4], al[2][4];
            #pragma unroll
            for (int mt = 0; mt < 2; mt++) {
                int mcol = wm * 32 + mt * 16 + mcs;
                uint32_t ad = stage_b + K1C_AHI * 4
                            + (uint32_t)(ks * 16 + krA) * 144 + mcol * 2;
                LDMATRIX_X4_T(ah[mt][0], ah[mt][1], ah[mt][2], ah[mt][3], ad);
                LDMATRIX_X4_T(al[mt][0], al[mt][1], al[mt][2], al[mt][3],
                              ad + (K1C_ALO - K1C_AHI) * 4);
            }
            #pragma unroll
            for (int j = 0; j < 2; j++) {
                int ncol = wn * 32 + j * 16 + ncs;
                uint32_t bd = stage_b + K1C_BHI * 4
                            + (uint32_t)(ks * 16 + krB) * 528 + ncol * 2;
                uint32_t bh0, bh1, bh2, bh3, bl0, bl1, bl2, bl3;
                LDMATRIX_X4_T(bh0, bh1, bh2, bh3, bd);
                LDMATRIX_X4_T(bl0, bl1, bl2, bl3, bd + (K1C_BLO - K1C_BHI) * 4);
                #pragma unroll
                for (int mt = 0; mt < 2; mt++) {
                    MMA_BF16(acc[mt][j * 2],     ah[mt][0], ah[mt][1], ah[mt][2], ah[mt][3], bh0, bh1);
                    MMA_BF16(acc[mt][j * 2 + 1], ah[mt][0], ah[mt][1], ah[mt][2], ah[mt][3], bh2, bh3);
                    MMA_BF16(acc[mt][j * 2],     ah[mt][0], ah[mt][1], ah[mt][2], ah[mt][3], bl0, bl1);
                    MMA_BF16(acc[mt][j * 2 + 1], ah[mt][0], ah[mt][1], ah[mt][2], ah[mt][3], bl2, bl3);
                    MMA_BF16(acc[mt][j * 2],     al[mt][0], al[mt][1], al[mt][2], al[mt][3], bh0, bh1);
                    MMA_BF16(acc[mt][j * 2 + 1], al[mt][0], al[mt][1], al[mt][2], al[mt][3], bh2, bh3);
                }
            }
        }

        if (c < 3) K1_ST((c + 1) & 1);
        __syncthreads();
    }

    // ---- scores: 64 rows x 261 fp32 (stride 261: odd -> conflict-free cols) ----
    float* sc = (float*)smc;
    const int gid = lane >> 2;
    const int tig = lane & 3;
    #pragma unroll
    for (int mt = 0; mt < 2; mt++) {
        int r0 = wm * 32 + mt * 16 + gid;
        #pragma unroll
        for (int nt = 0; nt < 4; nt++) {
            int q = wn * 32 + nt * 8 + tig * 2;
            sc[(size_t)r0 * 261 + q]           = acc[mt][nt][0];
            sc[(size_t)r0 * 261 + q + 1]       = acc[mt][nt][1];
            sc[(size_t)(r0 + 8) * 261 + q]     = acc[mt][nt][2];
            sc[(size_t)(r0 + 8) * 261 + q + 1] = acc[mt][nt][3];
        }
    }
    __syncthreads();

    // ---- softmax over Q, normalized IN PLACE (warp wid owns rows wid*4..+3) ----
    #pragma unroll
    for (int i = 0; i < 4; i++) {
        float* row = sc + (size_t)(wid * 4 + i) * 261;
        float e[8];
        float m = -1e30f;
        #pragma unroll
        for (int j = 0; j < 8; j++) { e[j] = row[lane + j * 32]; m = fmaxf(m, e[j]); }
        #pragma unroll
        for (int o = 16; o; o >>= 1) m = fmaxf(m, __shfl_xor_sync(0xffffffffu, m, o));
        float s = 0.0f;
        #pragma unroll
        for (int j = 0; j < 8; j++) { e[j] = __expf(e[j] - m); s += e[j]; }
        #pragma unroll
        for (int o = 16; o; o >>= 1) s += __shfl_xor_sync(0xffffffffu, s, o);
        float inv = 1.0f / s;
        #pragma unroll
        for (int j = 0; j < 8; j++) row[lane + j * 32] = e[j] * inv;
    }
    __syncthreads();

    // ---- transposed output: g_attn_q[b][q][l0 + l] (coalesced 128B stores) ----
    #pragma unroll
    for (int qi = 0; qi < 16; qi++) {
        int q = wid * 16 + qi;
        float v1 = sc[(size_t)lane * 261 + q];
        float v2 = sc[(size_t)(lane + 32) * 261 + q];
        float* dst = g_attn_q + ((size_t)b * QQ + q) * LL + l0;
        dst[lane]      = v1;
        dst[lane + 32] = v2;
    }
}

// ---------------------------------------------------------------------------
// Kernel 3 v2 (streaming): attn_c[b,q,l] = exp(4*aq_t[b,q,l]) / sum_l(...).
// aq_t values are in (0,1) -> no max pass needed (exp <= e^4).
// Warp per q; block 256 (8 q), grid (QQ/8, B). No smem. Coalesced float4 I/O.
// ---------------------------------------------------------------------------
__global__ __launch_bounds__(256)
void k3_softmax_l(float* __restrict__ amap) {
    const int w    = threadIdx.x >> 5;
    const int lane = threadIdx.x & 31;
    const int b    = blockIdx.y;
    const int q    = blockIdx.x * 8 + w;

    const float4* src = (const float4*)(g_attn_q + ((size_t)b * QQ + q) * LL);
    float e[32];
    float s = 0.0f;
    #pragma unroll
    for (int t = 0; t < 8; t++) {
        float4 v = src[t * 32 + lane];
        float e0 = __expf(TEMP * v.x);
        float e1 = __expf(TEMP * v.y);
        float e2 = __expf(TEMP * v.z);
        float e3 = __expf(TEMP * v.w);
        e[t * 4 + 0] = e0; e[t * 4 + 1] = e1;
        e[t * 4 + 2] = e2; e[t * 4 + 3] = e3;
        s += (e0 + e1) + (e2 + e3);
    }
    #pragma unroll
    for (int o = 16; o; o >>= 1) s += __shfl_xor_sync(0xffffffffu, s, o);
    const float inv = 1.0f / s;

    float4* dst = (float4*)(amap + ((size_t)b * QQ + q) * LL);
    #pragma unroll
    for (int t = 0; t < 8; t++) {
        dst[t * 32 + lane] = make_float4(e[t * 4 + 0] * inv, e[t * 4 + 1] * inv,
                                         e[t * 4 + 2] * inv, e[t * 4 + 3] * inv);
    }
}

// ---------------------------------------------------------------------------
// Kernel 4 v2 (HMMA bf16 split, double-buffered): unchanged from R13.
// ---------------------------------------------------------------------------
#define KC    32
#define NCH   (LL / KC)
#define ROWU  20
#define AHI_O 0
#define ALO_O (64 * ROWU)
#define BHI_O (2 * 64 * ROWU)
#define BLO_O (2 * 64 * ROWU + 128 * ROWU)
#define K4_STAGE_U 7680
#define K4_SMEM_BYTES (2 * K4_STAGE_U * 4)

__global__ __launch_bounds__(256, 2)
void k4_mma(const float* __restrict__ ctx,
            const float* __restrict__ amap,
            float* __restrict__ wc) {
    extern __shared__ __align__(16) uint32_t sm4[];
    const uint32_t sb = smem_u32(sm4);

    const int tid  = threadIdx.x;
    const int lane = tid & 31;
    const int wid  = tid >> 5;
    const int wm   = wid & 1;
    const int wn   = wid >> 1;

    const int b  = blockIdx.y;
    const int d0 = (blockIdx.x & 1) * 64;
    const int q0 = (blockIdx.x >> 1) * 128;

    const float* A  = ctx  + (size_t)b * DD * LL + (size_t)d0 * LL;
    const float* Bm = amap + ((size_t)b * QQ + q0) * LL;

    const int frow = tid >> 3;
    const int ff   = tid & 7;

    float4 pa0, pa1, pb0, pb1, pb2, pb3;

#define K4_LD(c) do { \
        const int _l0 = (c) * KC; \
        pa0 = *(const float4*)(A  + (size_t)(frow)      * LL + _l0 + ff * 4); \
        pa1 = *(const float4*)(A  + (size_t)(frow + 32) * LL + _l0 + ff * 4); \
        pb0 = *(const float4*)(Bm + (size_t)(frow)      * LL + _l0 + ff * 4); \
        pb1 = *(const float4*)(Bm + (size_t)(frow + 32) * LL + _l0 + ff * 4); \
        pb2 = *(const float4*)(Bm + (size_t)(frow + 64) * LL + _l0 + ff * 4); \
        pb3 = *(const float4*)(Bm + (size_t)(frow + 96) * LL + _l0 + ff * 4); \
    } while (0)

#define K4_ST1(v, base, row, lo_delta) do { \
        uint32_t _h0, _o0, _h1, _o1; \
        split2((v).x, (v).y, _h0, _o0); \
        split2((v).z, (v).w, _h1, _o1); \
        uint32_t* _p = stp + (base) + (row) * ROWU + ff * 2; \
        _p[0] = _h0; _p[1] = _h1; \
        _p[(lo_delta)] = _o0; _p[(lo_delta) + 1] = _o1; \
    } while (0)

#define K4_ST(s) do { \
        uint32_t* stp = sm4 + (s) * K4_STAGE_U; \
        K4_ST1(pa0, AHI_O, frow,       (ALO_O - AHI_O)); \
        K4_ST1(pa1, AHI_O, frow + 32,  (ALO_O - AHI_O)); \
        K4_ST1(pb0, BHI_O, frow,       (BLO_O - BHI_O)); \
        K4_ST1(pb1, BHI_O, frow + 32,  (BLO_O - BHI_O)); \
        K4_ST1(pb2, BHI_O, frow + 64,  (BLO_O - BHI_O)); \
        K4_ST1(pb3, BHI_O, frow + 96,  (BLO_O - BHI_O)); \
    } while (0)

    float acc[2][4][4];
    #pragma unroll
    for (int i = 0; i < 2; i++)
        #pragma unroll
        for (int j = 0; j < 4; j++)
            #pragma unroll
            for (int k = 0; k < 4; k++) acc[i][j][k] = 0.0f;

    const uint32_t a_row = wm * 32 + (lane & 15);
    const uint32_t a_col = (lane >> 4) * 16;
    const uint32_t b_rowbase = wn * 32 + ((lane >> 4) << 3) + (lane & 7);
    const uint32_t b_col = ((lane >> 3) & 1) * 16;

    K4_LD(0);
    K4_ST(0);
    __syncthreads();

    for (int c = 0; c < NCH; c++) {
        if (c < NCH - 1) K4_LD(c + 1);

        const uint32_t stage_b = sb + (uint32_t)(c & 1) * (K4_STAGE_U * 4);
        #pragma unroll
        for (int ks = 0; ks < 2; ks++) {
            const uint32_t kbyte = ks * 32;
            uint32_t ah[2][4], al[2][4];
            #pragma unroll
            for (int mt = 0; mt < 2; mt++) {
                uint32_t addr = stage_b + 4 * (AHI_O + (a_row + mt * 16) * ROWU)
                              + kbyte + a_col;
                LDMATRIX_X4(ah[mt][0], ah[mt][1], ah[mt][2], ah[mt][3], addr);
                addr += 4 * (ALO_O - AHI_O);
                LDMATRIX_X4(al[mt][0], al[mt][1], al[mt][2], al[mt][3], addr);
            }
            uint32_t bh[4][2], bl[4][2];
            #pragma unroll
            for (int p = 0; p < 2; p++) {
                uint32_t addr = stage_b + 4 * (BHI_O + (b_rowbase + p * 16) * ROWU)
                              + kbyte + b_col;
                LDMATRIX_X4(bh[p * 2][0], bh[p * 2][1],
                            bh[p * 2 + 1][0], bh[p * 2 + 1][1], addr);
                addr += 4 * (BLO_O - BHI_O);
                LDMATRIX_X4(bl[p * 2][0], bl[p * 2][1],
                            bl[p * 2 + 1][0], bl[p * 2 + 1][1], addr);
            }
            #pragma unroll
            for (int mt = 0; mt < 2; mt++)
                #pragma unroll
                for (int nt = 0; nt < 4; nt++)
                    MMA_BF16(acc[mt][nt], ah[mt][0], ah[mt][1], ah[mt][2],
                             ah[mt][3], bh[nt][0], bh[nt][1]);
            #pragma unroll
            for (int mt = 0; mt < 2; mt++)
                #pragma unroll
                for (int nt = 0; nt < 4; nt++)
                    MMA_BF16(acc[mt][nt], ah[mt][0], ah[mt][1], ah[mt][2],
                             ah[mt][3], bl[nt][0], bl[nt][1]);
            #pragma unroll
            for (int mt = 0; mt < 2; mt++)
                #pragma unroll
                for (int nt = 0; nt < 4; nt++)
                    MMA_BF16(acc[mt][nt], al[mt][0], al[mt][1], al[mt][2],
                             al[mt][3], bh[nt][0], bh[nt][1]);
        }

        if (c < NCH - 1) K4_ST((c + 1) & 1);
        __syncthreads();
    }

    float* outb = wc + (size_t)b * DD * QQ;
    const int gid = lane >> 2;
    const int tig = lane & 3;
    #pragma unroll
    for (int mt = 0; mt < 2; mt++) {
        #pragma unroll
        for (int nt = 0; nt < 4; nt++) {
            int d = d0 + wm * 32 + mt * 16 + gid;
            int q = q0 + wn * 32 + nt * 8 + tig * 2;
            *(float2*)(outb + (size_t)d * QQ + q) =
                make_float2(acc[mt][nt][0], acc[mt][nt][1]);
            *(float2*)(outb + (size_t)(d + 8) * QQ + q) =
                make_float2(acc[mt][nt][2], acc[mt][nt][3]);
        }
    }
}

// ---------------------------------------------------------------------------
extern "C" void kernel_launch(void* const* d_in, const int* in_sizes, int n_in,
                              void* d_out, int out_size) {
    const float* query;
    const float* ctx;
    if ((size_t)in_sizes[0] == QUERY_ELEMS) {
        query = (const float*)d_in[0];
        ctx   = (const float*)d_in[1];
    } else {
        query = (const float*)d_in[1];
        ctx   = (const float*)d_in[0];
    }

    float* wc;
    float* amap;
    void* sym;
    if ((size_t)out_size >= WC_ELEMS + AMAP_ELEMS) {
        wc   = (float*)d_out;
        amap = (float*)d_out + WC_ELEMS;
    } else if ((size_t)out_size == WC_ELEMS) {
        wc = (float*)d_out;
        cudaGetSymbolAddress(&sym, g_scratch_amap);
        amap = (float*)sym;
    } else {
        cudaGetSymbolAddress(&sym, g_scratch_wc);
        wc = (float*)sym;
        amap = (float*)d_out;
    }

    cudaFuncSetAttribute(k1_mma,
                         cudaFuncAttributeMaxDynamicSharedMemorySize, K1_SMEM_BYTES);
    cudaFuncSetAttribute(k4_mma,
                         cudaFuncAttributeMaxDynamicSharedMemorySize, K4_SMEM_BYTES);

    k1_mma<<<dim3(LL / 64, BB), 512, K1_SMEM_BYTES>>>(query, ctx);
    k3_softmax_l<<<dim3(QQ / 8, BB), 256>>>(amap);
    k4_mma<<<dim3(4, BB), 256, K4_SMEM_BYTES>>>(ctx, amap, wc);
}

// round 17
// speedup vs baseline: 1.0629x; 1.0180x over previous
#include <cuda_runtime.h>
#include <cuda_bf16.h>
#include <cstdint>
#include <math.h>

#define BB 128
#define DD 128
#define QQ 256
#define LL 1024
#define TEMP 4.0f

#define QUERY_ELEMS ((size_t)BB * DD * QQ)
#define WC_ELEMS    ((size_t)BB * DD * QQ)
#define AMAP_ELEMS  ((size_t)BB * QQ * LL)

// g_attn_q is stored TRANSPOSED: [b][q][l]
__device__ __align__(16) float g_attn_q[(size_t)BB * QQ * LL];
__device__ __align__(16) float g_scratch_amap[AMAP_ELEMS];
__device__ __align__(16) float g_scratch_wc[WC_ELEMS];

// ============================ helpers ======================================
__device__ __forceinline__ uint32_t smem_u32(const void* p) {
    uint32_t a;
    asm("{ .reg .u64 t; cvta.to.shared.u64 t, %1; cvt.u32.u64 %0, t; }"
        : "=r"(a) : "l"(p));
    return a;
}
__device__ __forceinline__ uint32_t pack2bf(float x, float y) {
    __nv_bfloat162 h = __floats2bfloat162_rn(x, y);
    return *(uint32_t*)&h;
}
__device__ __forceinline__ void split2(float x, float y,
                                       uint32_t& hi, uint32_t& lo) {
    __nv_bfloat16 hx = __float2bfloat16_rn(x);
    __nv_bfloat16 hy = __float2bfloat16_rn(y);
    float rx = x - __bfloat162float(hx);
    float ry = y - __bfloat162float(hy);
    __nv_bfloat162 h2; h2.x = hx; h2.y = hy;
    hi = *(uint32_t*)&h2;
    lo = pack2bf(rx, ry);
}
#define LDMATRIX_X4(r0, r1, r2, r3, addr) \
    asm volatile("ldmatrix.sync.aligned.m8n8.x4.shared.b16 {%0,%1,%2,%3}, [%4];" \
                 : "=r"(r0), "=r"(r1), "=r"(r2), "=r"(r3) : "r"(addr))
#define LDMATRIX_X4_T(r0, r1, r2, r3, addr) \
    asm volatile("ldmatrix.sync.aligned.m8n8.x4.trans.shared.b16 {%0,%1,%2,%3}, [%4];" \
                 : "=r"(r0), "=r"(r1), "=r"(r2), "=r"(r3) : "r"(addr))
#define MMA_BF16(c, a0, a1, a2, a3, b0, b1) \
    asm volatile("mma.sync.aligned.m16n8k16.row.col.f32.bf16.bf16.f32 " \
                 "{%0,%1,%2,%3}, {%4,%5,%6,%7}, {%8,%9}, {%0,%1,%2,%3};" \
                 : "+f"((c)[0]), "+f"((c)[1]), "+f"((c)[2]), "+f"((c)[3]) \
                 : "r"(a0), "r"(a1), "r"(a2), "r"(a3), "r"(b0), "r"(b1))

// ---------------------------------------------------------------------------
// Kernel 1 v6: CTA 64(l) x 128(q), 256 threads, 2 CTAs/SM.
// grid (32, B): l0 = (x>>1)*64, q0 = (x&1)*128.
// 8 warps = 2(m) x 4(n); warp tile 32x32; acc 32 regs.
// Stage (u32): AHI[32x36]=1152 ALO=1152 BHI[32x68]=2176 BLO=2176 -> 6656.
// Two stages = 53,248 B. Epilogue reuses smem as scores[64][129] fp32,
// writes g_attn_q transposed [b][q][l].
// ---------------------------------------------------------------------------
#define K1C_AHI 0
#define K1C_ALO 1152
#define K1C_BHI 2304
#define K1C_BLO 4480
#define K1_STAGE_U 6656
#define K1_SMEM_BYTES (2 * K1_STAGE_U * 4)   // 53248 B

__global__ __launch_bounds__(256, 2)
void k1_mma(const float* __restrict__ query,
            const float* __restrict__ ctx) {
    extern __shared__ __align__(16) char smc[];
    uint32_t* smu = (uint32_t*)smc;
    const uint32_t sb = smem_u32(smc);

    const int tid  = threadIdx.x;
    const int lane = tid & 31;
    const int wid  = tid >> 5;       // 0..7
    const int wm   = wid & 1;        // 32 l-rows
    const int wn   = wid >> 1;       // 0..3 : 32 q-cols

    const int b  = blockIdx.y;
    const int l0 = (blockIdx.x >> 1) * 64;
    const int q0 = (blockIdx.x & 1) * 128;

    const float* ctxb = ctx + (size_t)b * DD * LL;
    const float* qb   = query + (size_t)b * DD * QQ + q0;

    // fill indices
    const int a_fl = tid & 15;       // float4 col along l (0..15)
    const int a_dr = tid >> 4;       // d-row 0..15 (also +16)
    const int b_fq = tid & 31;       // float4 col along q (0..31)
    const int b_dr = tid >> 5;       // d-row base 0..7 (+8,+16,+24)

    float4 pa0, pa1, pb0, pb1, pb2, pb3;

#define K1_LD(c) do { \
        const int _d0 = (c) * 32; \
        pa0 = *(const float4*)(ctxb + (size_t)(_d0 + a_dr)      * LL + l0 + a_fl * 4); \
        pa1 = *(const float4*)(ctxb + (size_t)(_d0 + a_dr + 16) * LL + l0 + a_fl * 4); \
        pb0 = *(const float4*)(qb + (size_t)(_d0 + b_dr)      * QQ + b_fq * 4); \
        pb1 = *(const float4*)(qb + (size_t)(_d0 + b_dr +  8) * QQ + b_fq * 4); \
        pb2 = *(const float4*)(qb + (size_t)(_d0 + b_dr + 16) * QQ + b_fq * 4); \
        pb3 = *(const float4*)(qb + (size_t)(_d0 + b_dr + 24) * QQ + b_fq * 4); \
    } while (0)

#define K1_ST1(v, base, row, stride_u, lo_delta, col) do { \
        uint32_t _h0, _o0, _h1, _o1; \
        split2((v).x, (v).y, _h0, _o0); \
        split2((v).z, (v).w, _h1, _o1); \
        uint32_t* _p = stp + (base) + (row) * (stride_u) + (col) * 2; \
        _p[0] = _h0; _p[1] = _h1; \
        _p[(lo_delta)] = _o0; _p[(lo_delta) + 1] = _o1; \
    } while (0)

#define K1_ST(s) do { \
        uint32_t* stp = smu + (s) * K1_STAGE_U; \
        K1_ST1(pa0, K1C_AHI, a_dr,      36, (K1C_ALO - K1C_AHI), a_fl); \
        K1_ST1(pa1, K1C_AHI, a_dr + 16, 36, (K1C_ALO - K1C_AHI), a_fl); \
        K1_ST1(pb0, K1C_BHI, b_dr,      68, (K1C_BLO - K1C_BHI), b_fq); \
        K1_ST1(pb1, K1C_BHI, b_dr + 8,  68, (K1C_BLO - K1C_BHI), b_fq); \
        K1_ST1(pb2, K1C_BHI, b_dr + 16, 68, (K1C_BLO - K1C_BHI), b_fq); \
        K1_ST1(pb3, K1C_BHI, b_dr + 24, 68, (K1C_BLO - K1C_BHI), b_fq); \
    } while (0)

    float acc[2][4][4];
    #pragma unroll
    for (int i = 0; i < 2; i++)
        #pragma unroll
        for (int j = 0; j < 4; j++)
            #pragma unroll
            for (int k = 0; k < 4; k++) acc[i][j][k] = 0.0f;

    const int krA = ((lane >> 4) << 3) + (lane & 7);
    const int mcs = (((lane >> 3) & 1) << 3);
    const int krB = (((lane >> 3) & 1) << 3) + (lane & 7);
    const int ncs = ((lane >> 4) << 3);

    K1_LD(0);
    K1_ST(0);
    __syncthreads();

    for (int c = 0; c < 4; c++) {
        if (c < 3) K1_LD(c + 1);

        const uint32_t stage_b = sb + (uint32_t)(c & 1) * (K1_STAGE_U * 4);
        #pragma unroll
        for (int ks = 0; ks < 2; ks++) {
            uint32_t ah[2][4], al[2][4];
            #pragma unroll
            for (int mt = 0; mt < 2; mt++) {
                int mcol = wm * 32 + mt * 16 + mcs;
                uint32_t ad = stage_b + K1C_AHI * 4
                            + (uint32_t)(ks * 16 + krA) * 144 + mcol * 2;
                LDMATRIX_X4_T(ah[mt][0], ah[mt][1], ah[mt][2], ah[mt][3], ad);
                LDMATRIX_X4_T(al[mt][0], al[mt][1], al[mt][2], al[mt][3],
                              ad + (K1C_ALO - K1C_AHI) * 4);
            }
            #pragma unroll
            for (int j = 0; j < 2; j++) {
                int ncol = wn * 32 + j * 16 + ncs;
                uint32_t bd = stage_b + K1C_BHI * 4
                            + (uint32_t)(ks * 16 + krB) * 272 + ncol * 2;
                uint32_t bh0, bh1, bh2, bh3, bl0, bl1, bl2, bl3;
                LDMATRIX_X4_T(bh0, bh1, bh2, bh3, bd);
                LDMATRIX_X4_T(bl0, bl1, bl2, bl3, bd + (K1C_BLO - K1C_BHI) * 4);
                #pragma unroll
                for (int mt = 0; mt < 2; mt++) {
                    MMA_BF16(acc[mt][j * 2],     ah[mt][0], ah[mt][1], ah[mt][2], ah[mt][3], bh0, bh1);
                    MMA_BF16(acc[mt][j * 2 + 1], ah[mt][0], ah[mt][1], ah[mt][2], ah[mt][3], bh2, bh3);
                    MMA_BF16(acc[mt][j * 2],     ah[mt][0], ah[mt][1], ah[mt][2], ah[mt][3], bl0, bl1);
                    MMA_BF16(acc[mt][j * 2 + 1], ah[mt][0], ah[mt][1], ah[mt][2], ah[mt][3], bl2, bl3);
                    MMA_BF16(acc[mt][j * 2],     al[mt][0], al[mt][1], al[mt][2], al[mt][3], bh0, bh1);
                    MMA_BF16(acc[mt][j * 2 + 1], al[mt][0], al[mt][1], al[mt][2], al[mt][3], bh2, bh3);
                }
            }
        }

        if (c < 3) K1_ST((c + 1) & 1);
        __syncthreads();
    }

    // ---- scores: 64 rows x 129 fp32 (stride 129 odd -> conflict-free) ----
    float* sc = (float*)smc;
    const int gid = lane >> 2;
    const int tig = lane & 3;
    #pragma unroll
    for (int mt = 0; mt < 2; mt++) {
        int r0 = wm * 32 + mt * 16 + gid;
        #pragma unroll
        for (int nt = 0; nt < 4; nt++) {
            int q = wn * 32 + nt * 8 + tig * 2;
            sc[(size_t)r0 * 129 + q]           = acc[mt][nt][0];
            sc[(size_t)r0 * 129 + q + 1]       = acc[mt][nt][1];
            sc[(size_t)(r0 + 8) * 129 + q]     = acc[mt][nt][2];
            sc[(size_t)(r0 + 8) * 129 + q + 1] = acc[mt][nt][3];
        }
    }
    __syncthreads();

    // ---- softmax over Q (full Q spans 2 CTAs? NO: softmax is over the FULL
    // q range... but this CTA only holds 128 q!  -> must reduce across q0.
    // The q-softmax denominator needs all 256 q; handled by sharing partial
    // sums through the paired CTA is not possible. Instead: softmax here is
    // computed per 128-q half and combined EXACTLY because both halves of a
    // row use the same max/sum only if computed globally. To stay exact, we
    // compute local max/sum, then write exp-shifted values scaled later?
    // NOT valid -> instead each CTA computes BOTH halves' statistics by
    // keeping the B tile of the other half? Simplest exact fix: each CTA
    // recomputes row stats from its own half plus the other half fetched
    // from a stats exchange. To avoid cross-CTA sync entirely, each CTA
    // covers the full row for the softmax by... (see below: we instead give
    // each CTA the full 256-q scores for its rows by splitting rows, not q).
    __syncthreads();
}

// NOTE: the q-split breaks the row softmax. Proper v6 splits by L instead:
// CTA 32(l) x 256(q). See k1_mma32 below, which is the kernel actually used.

// ---------------------------------------------------------------------------
// Kernel 1 v6b: CTA 32(l) x 256(q), 256 threads, 2 CTAs/SM. grid (32, B).
// Full q-row resident -> softmax exact. 8 warps = 1(m) x 8(n), warp 32x32.
// Stage (u32): AHI[32x20]=640 ALO=640 BHI[32x132]=4224 BLO=4224 -> 9728.
// Two stages = 77,824 B; 2 CTAs/SM = 155,648 B < 227 KB. regs target <=128.
// Scores reuse: 32 x 261 fp32 = 33,408 B.
// ---------------------------------------------------------------------------
#define V6_AHI 0
#define V6_ALO 640
#define V6_BHI 1280
#define V6_BLO 5504
#define V6_STAGE_U 9728
#define V6_SMEM_BYTES (2 * V6_STAGE_U * 4)   // 77824 B

__global__ __launch_bounds__(256, 2)
void k1_mma32(const float* __restrict__ query,
              const float* __restrict__ ctx) {
    extern __shared__ __align__(16) char smc[];
    uint32_t* smu = (uint32_t*)smc;
    const uint32_t sb = smem_u32(smc);

    const int tid  = threadIdx.x;
    const int lane = tid & 31;
    const int wid  = tid >> 5;       // 0..7 : 32 q-cols each (m spans all 32 l)
    const int b    = blockIdx.y;
    const int l0   = blockIdx.x * 32;

    const float* ctxb = ctx + (size_t)b * DD * LL;
    const float* qb   = query + (size_t)b * DD * QQ;

    // fill indices: A chunk 32d x 32l = 256 float4 -> 1/thread.
    const int a_fl = tid & 7;        // float4 col along l (0..7)
    const int a_dr = tid >> 3;       // d-row 0..31
    // B chunk 32d x 256q = 2048 float4 -> 8/thread.
    const int b_fq = tid & 63;       // float4 col along q (0..63)
    const int b_dr = tid >> 6;       // d-row base 0..3 (+4 steps x8)

    float4 pa, pb[8];

#define V6_LD(c) do { \
        const int _d0 = (c) * 32; \
        pa = *(const float4*)(ctxb + (size_t)(_d0 + a_dr) * LL + l0 + a_fl * 4); \
        _Pragma("unroll") \
        for (int _r = 0; _r < 8; _r++) \
            pb[_r] = *(const float4*)(qb + (size_t)(_d0 + b_dr + _r * 4) * QQ + b_fq * 4); \
    } while (0)

#define V6_ST1(v, base, row, stride_u, lo_delta, col) do { \
        uint32_t _h0, _o0, _h1, _o1; \
        split2((v).x, (v).y, _h0, _o0); \
        split2((v).z, (v).w, _h1, _o1); \
        uint32_t* _p = stp + (base) + (row) * (stride_u) + (col) * 2; \
        _p[0] = _h0; _p[1] = _h1; \
        _p[(lo_delta)] = _o0; _p[(lo_delta) + 1] = _o1; \
    } while (0)

#define V6_ST(s) do { \
        uint32_t* stp = smu + (s) * V6_STAGE_U; \
        V6_ST1(pa, V6_AHI, a_dr, 20, (V6_ALO - V6_AHI), a_fl); \
        _Pragma("unroll") \
        for (int _r = 0; _r < 8; _r++) \
            V6_ST1(pb[_r], V6_BHI, b_dr + _r * 4, 132, (V6_BLO - V6_BHI), b_fq); \
    } while (0)

    float acc[2][4][4];
    #pragma unroll
    for (int i = 0; i < 2; i++)
        #pragma unroll
        for (int j = 0; j < 4; j++)
            #pragma unroll
            for (int k = 0; k < 4; k++) acc[i][j][k] = 0.0f;

    const int krA = ((lane >> 4) << 3) + (lane & 7);
    const int mcs = (((lane >> 3) & 1) << 3);
    const int krB = (((lane >> 3) & 1) << 3) + (lane & 7);
    const int ncs = ((lane >> 4) << 3);

    V6_LD(0);
    V6_ST(0);
    __syncthreads();

    for (int c = 0; c < 4; c++) {
        if (c < 3) V6_LD(c + 1);

        const uint32_t stage_b = sb + (uint32_t)(c & 1) * (V6_STAGE_U * 4);
        #pragma unroll
        for (int ks = 0; ks < 2; ks++) {
            // A: rows = 32 l (mt 0..1 over 16-l tiles), row stride 80 B
            uint32_t ah[2][4], al[2][4];
            #pragma unroll
            for (int mt = 0; mt < 2; mt++) {
                int mcol = mt * 16 + mcs;
                uint32_t ad = stage_b + V6_AHI * 4
                            + (uint32_t)(ks * 16 + krA) * 80 + mcol * 2;
                LDMATRIX_X4_T(ah[mt][0], ah[mt][1], ah[mt][2], ah[mt][3], ad);
                LDMATRIX_X4_T(al[mt][0], al[mt][1], al[mt][2], al[mt][3],
                              ad + (V6_ALO - V6_AHI) * 4);
            }
            #pragma unroll
            for (int j = 0; j < 2; j++) {
                int ncol = wid * 32 + j * 16 + ncs;
                uint32_t bd = stage_b + V6_BHI * 4
                            + (uint32_t)(ks * 16 + krB) * 528 + ncol * 2;
                uint32_t bh0, bh1, bh2, bh3, bl0, bl1, bl2, bl3;
                LDMATRIX_X4_T(bh0, bh1, bh2, bh3, bd);
                LDMATRIX_X4_T(bl0, bl1, bl2, bl3, bd + (V6_BLO - V6_BHI) * 4);
                #pragma unroll
                for (int mt = 0; mt < 2; mt++) {
                    MMA_BF16(acc[mt][j * 2],     ah[mt][0], ah[mt][1], ah[mt][2], ah[mt][3], bh0, bh1);
                    MMA_BF16(acc[mt][j * 2 + 1], ah[mt][0], ah[mt][1], ah[mt][2], ah[mt][3], bh2, bh3);
                    MMA_BF16(acc[mt][j * 2],     ah[mt][0], ah[mt][1], ah[mt][2], ah[mt][3], bl0, bl1);
                    MMA_BF16(acc[mt][j * 2 + 1], ah[mt][0], ah[mt][1], ah[mt][2], ah[mt][3], bl2, bl3);
                    MMA_BF16(acc[mt][j * 2],     al[mt][0], al[mt][1], al[mt][2], al[mt][3], bh0, bh1);
                    MMA_BF16(acc[mt][j * 2 + 1], al[mt][0], al[mt][1], al[mt][2], al[mt][3], bh2, bh3);
                }
            }
        }

        if (c < 3) V6_ST((c + 1) & 1);
        __syncthreads();
    }

    // ---- scores: 32 rows x 261 fp32 ----
    float* sc = (float*)smc;
    const int gid = lane >> 2;
    const int tig = lane & 3;
    #pragma unroll
    for (int mt = 0; mt < 2; mt++) {
        int r0 = mt * 16 + gid;
        #pragma unroll
        for (int nt = 0; nt < 4; nt++) {
            int q = wid * 32 + nt * 8 + tig * 2;
            sc[(size_t)r0 * 261 + q]           = acc[mt][nt][0];
            sc[(size_t)r0 * 261 + q + 1]       = acc[mt][nt][1];
            sc[(size_t)(r0 + 8) * 261 + q]     = acc[mt][nt][2];
            sc[(size_t)(r0 + 8) * 261 + q + 1] = acc[mt][nt][3];
        }
    }
    __syncthreads();

    // ---- softmax over Q (full 256 resident), in place. warp wid: rows wid*4..+3 ----
    #pragma unroll
    for (int i = 0; i < 4; i++) {
        float* row = sc + (size_t)(wid * 4 + i) * 261;
        float e[8];
        float m = -1e30f;
        #pragma unroll
        for (int j = 0; j < 8; j++) { e[j] = row[lane + j * 32]; m = fmaxf(m, e[j]); }
        #pragma unroll
        for (int o = 16; o; o >>= 1) m = fmaxf(m, __shfl_xor_sync(0xffffffffu, m, o));
        float s = 0.0f;
        #pragma unroll
        for (int j = 0; j < 8; j++) { e[j] = __expf(e[j] - m); s += e[j]; }
        #pragma unroll
        for (int o = 16; o; o >>= 1) s += __shfl_xor_sync(0xffffffffu, s, o);
        float inv = 1.0f / s;
        #pragma unroll
        for (int j = 0; j < 8; j++) row[lane + j * 32] = e[j] * inv;
    }
    __syncthreads();

    // ---- transposed output: g_attn_q[b][q][l0..l0+31] (32 q per warp) ----
    #pragma unroll
    for (int qi = 0; qi < 32; qi++) {
        int q = wid * 32 + qi;
        float v = sc[(size_t)lane * 261 + q];
        g_attn_q[((size_t)b * QQ + q) * LL + l0 + lane] = v;
    }
}

// ---------------------------------------------------------------------------
// Kernel 3 v2 (streaming, no max pass): unchanged from R16.
// ---------------------------------------------------------------------------
__global__ __launch_bounds__(256)
void k3_softmax_l(float* __restrict__ amap) {
    const int w    = threadIdx.x >> 5;
    const int lane = threadIdx.x & 31;
    const int b    = blockIdx.y;
    const int q    = blockIdx.x * 8 + w;

    const float4* src = (const float4*)(g_attn_q + ((size_t)b * QQ + q) * LL);
    float e[32];
    float s = 0.0f;
    #pragma unroll
    for (int t = 0; t < 8; t++) {
        float4 v = src[t * 32 + lane];
        float e0 = __expf(TEMP * v.x);
        float e1 = __expf(TEMP * v.y);
        float e2 = __expf(TEMP * v.z);
        float e3 = __expf(TEMP * v.w);
        e[t * 4 + 0] = e0; e[t * 4 + 1] = e1;
        e[t * 4 + 2] = e2; e[t * 4 + 3] = e3;
        s += (e0 + e1) + (e2 + e3);
    }
    #pragma unroll
    for (int o = 16; o; o >>= 1) s += __shfl_xor_sync(0xffffffffu, s, o);
    const float inv = 1.0f / s;

    float4* dst = (float4*)(amap + ((size_t)b * QQ + q) * LL);
    #pragma unroll
    for (int t = 0; t < 8; t++) {
        dst[t * 32 + lane] = make_float4(e[t * 4 + 0] * inv, e[t * 4 + 1] * inv,
                                         e[t * 4 + 2] * inv, e[t * 4 + 3] * inv);
    }
}

// ---------------------------------------------------------------------------
// Kernel 4 v2 (HMMA bf16 split, double-buffered): unchanged from R13.
// ---------------------------------------------------------------------------
#define KC    32
#define NCH   (LL / KC)
#define ROWU  20
#define AHI_O 0
#define ALO_O (64 * ROWU)
#define BHI_O (2 * 64 * ROWU)
#define BLO_O (2 * 64 * ROWU + 128 * ROWU)
#define K4_STAGE_U 7680
#define K4_SMEM_BYTES (2 * K4_STAGE_U * 4)

__global__ __launch_bounds__(256, 2)
void k4_mma(const float* __restrict__ ctx,
            const float* __restrict__ amap,
            float* __restrict__ wc) {
    extern __shared__ __align__(16) uint32_t sm4[];
    const uint32_t sb = smem_u32(sm4);

    const int tid  = threadIdx.x;
    const int lane = tid & 31;
    const int wid  = tid >> 5;
    const int wm   = wid & 1;
    const int wn   = wid >> 1;

    const int b  = blockIdx.y;
    const int d0 = (blockIdx.x & 1) * 64;
    const int q0 = (blockIdx.x >> 1) * 128;

    const float* A  = ctx  + (size_t)b * DD * LL + (size_t)d0 * LL;
    const float* Bm = amap + ((size_t)b * QQ + q0) * LL;

    const int frow = tid >> 3;
    const int ff   = tid & 7;

    float4 pa0, pa1, pb0, pb1, pb2, pb3;

#define K4_LD(c) do { \
        const int _l0 = (c) * KC; \
        pa0 = *(const float4*)(A  + (size_t)(frow)      * LL + _l0 + ff * 4); \
        pa1 = *(const float4*)(A  + (size_t)(frow + 32) * LL + _l0 + ff * 4); \
        pb0 = *(const float4*)(Bm + (size_t)(frow)      * LL + _l0 + ff * 4); \
        pb1 = *(const float4*)(Bm + (size_t)(frow + 32) * LL + _l0 + ff * 4); \
        pb2 = *(const float4*)(Bm + (size_t)(frow + 64) * LL + _l0 + ff * 4); \
        pb3 = *(const float4*)(Bm + (size_t)(frow + 96) * LL + _l0 + ff * 4); \
    } while (0)

#define K4_ST1(v, base, row, lo_delta) do { \
        uint32_t _h0, _o0, _h1, _o1; \
        split2((v).x, (v).y, _h0, _o0); \
        split2((v).z, (v).w, _h1, _o1); \
        uint32_t* _p = stp + (base) + (row) * ROWU + ff * 2; \
        _p[0] = _h0; _p[1] = _h1; \
        _p[(lo_delta)] = _o0; _p[(lo_delta) + 1] = _o1; \
    } while (0)

#define K4_ST(s) do { \
        uint32_t* stp = sm4 + (s) * K4_STAGE_U; \
        K4_ST1(pa0, AHI_O, frow,       (ALO_O - AHI_O)); \
        K4_ST1(pa1, AHI_O, frow + 32,  (ALO_O - AHI_O)); \
        K4_ST1(pb0, BHI_O, frow,       (BLO_O - BHI_O)); \
        K4_ST1(pb1, BHI_O, frow + 32,  (BLO_O - BHI_O)); \
        K4_ST1(pb2, BHI_O, frow + 64,  (BLO_O - BHI_O)); \
        K4_ST1(pb3, BHI_O, frow + 96,  (BLO_O - BHI_O)); \
    } while (0)

    float acc[2][4][4];
    #pragma unroll
    for (int i = 0; i < 2; i++)
        #pragma unroll
        for (int j = 0; j < 4; j++)
            #pragma unroll
            for (int k = 0; k < 4; k++) acc[i][j][k] = 0.0f;

    const uint32_t a_row = wm * 32 + (lane & 15);
    const uint32_t a_col = (lane >> 4) * 16;
    const uint32_t b_rowbase = wn * 32 + ((lane >> 4) << 3) + (lane & 7);
    const uint32_t b_col = ((lane >> 3) & 1) * 16;

    K4_LD(0);
    K4_ST(0);
    __syncthreads();

    for (int c = 0; c < NCH; c++) {
        if (c < NCH - 1) K4_LD(c + 1);

        const uint32_t stage_b = sb + (uint32_t)(c & 1) * (K4_STAGE_U * 4);
        #pragma unroll
        for (int ks = 0; ks < 2; ks++) {
            const uint32_t kbyte = ks * 32;
            uint32_t ah[2][4], al[2][4];
            #pragma unroll
            for (int mt = 0; mt < 2; mt++) {
                uint32_t addr = stage_b + 4 * (AHI_O + (a_row + mt * 16) * ROWU)
                              + kbyte + a_col;
                LDMATRIX_X4(ah[mt][0], ah[mt][1], ah[mt][2], ah[mt][3], addr);
                addr += 4 * (ALO_O - AHI_O);
                LDMATRIX_X4(al[mt][0], al[mt][1], al[mt][2], al[mt][3], addr);
            }
            uint32_t bh[4][2], bl[4][2];
            #pragma unroll
            for (int p = 0; p < 2; p++) {
                uint32_t addr = stage_b + 4 * (BHI_O + (b_rowbase + p * 16) * ROWU)
                              + kbyte + b_col;
                LDMATRIX_X4(bh[p * 2][0], bh[p * 2][1],
                            bh[p * 2 + 1][0], bh[p * 2 + 1][1], addr);
                addr += 4 * (BLO_O - BHI_O);
                LDMATRIX_X4(bl[p * 2][0], bl[p * 2][1],
                            bl[p * 2 + 1][0], bl[p * 2 + 1][1], addr);
            }
            #pragma unroll
            for (int mt = 0; mt < 2; mt++)
                #pragma unroll
                for (int nt = 0; nt < 4; nt++)
                    MMA_BF16(acc[mt][nt], ah[mt][0], ah[mt][1], ah[mt][2],
                             ah[mt][3], bh[nt][0], bh[nt][1]);
            #pragma unroll
            for (int mt = 0; mt < 2; mt++)
                #pragma unroll
                for (int nt = 0; nt < 4; nt++)
                    MMA_BF16(acc[mt][nt], ah[mt][0], ah[mt][1], ah[mt][2],
                             ah[mt][3], bl[nt][0], bl[nt][1]);
            #pragma unroll
            for (int mt = 0; mt < 2; mt++)
                #pragma unroll
                for (int nt = 0; nt < 4; nt++)
                    MMA_BF16(acc[mt][nt], al[mt][0], al[mt][1], al[mt][2],
                             al[mt][3], bh[nt][0], bh[nt][1]);
        }

        if (c < NCH - 1) K4_ST((c + 1) & 1);
        __syncthreads();
    }

    float* outb = wc + (size_t)b * DD * QQ;
    const int gid = lane >> 2;
    const int tig = lane & 3;
    #pragma unroll
    for (int mt = 0; mt < 2; mt++) {
        #pragma unroll
        for (int nt = 0; nt < 4; nt++) {
            int d = d0 + wm * 32 + mt * 16 + gid;
            int q = q0 + wn * 32 + nt * 8 + tig * 2;
            *(float2*)(outb + (size_t)d * QQ + q) =
                make_float2(acc[mt][nt][0], acc[mt][nt][1]);
            *(float2*)(outb + (size_t)(d + 8) * QQ + q) =
                make_float2(acc[mt][nt][2], acc[mt][nt][3]);
        }
    }
}

// ---------------------------------------------------------------------------
extern "C" void kernel_launch(void* const* d_in, const int* in_sizes, int n_in,
                              void* d_out, int out_size) {
    const float* query;
    const float* ctx;
    if ((size_t)in_sizes[0] == QUERY_ELEMS) {
        query = (const float*)d_in[0];
        ctx   = (const float*)d_in[1];
    } else {
        query = (const float*)d_in[1];
        ctx   = (const float*)d_in[0];
    }

    float* wc;
    float* amap;
    void* sym;
    if ((size_t)out_size >= WC_ELEMS + AMAP_ELEMS) {
        wc   = (float*)d_out;
        amap = (float*)d_out + WC_ELEMS;
    } else if ((size_t)out_size == WC_ELEMS) {
        wc = (float*)d_out;
        cudaGetSymbolAddress(&sym, g_scratch_amap);
        amap = (float*)sym;
    } else {
        cudaGetSymbolAddress(&sym, g_scratch_wc);
        wc = (float*)sym;
        amap = (float*)d_out;
    }

    cudaFuncSetAttribute(k1_mma32,
                         cudaFuncAttributeMaxDynamicSharedMemorySize, V6_SMEM_BYTES);
    cudaFuncSetAttribute(k4_mma,
                         cudaFuncAttributeMaxDynamicSharedMemorySize, K4_SMEM_BYTES);

    k1_mma32<<<dim3(LL / 32, BB), 256, V6_SMEM_BYTES>>>(query, ctx);
    k3_softmax_l<<<dim3(QQ / 8, BB), 256>>>(amap);
    k4_mma<<<dim3(4, BB), 256, K4_SMEM_BYTES>>>(ctx, amap, wc);
}